// round 1
// baseline (speedup 1.0000x reference)
#include <cuda_runtime.h>
#include <cstdint>
#include <cstddef>

// Problem constants
// T=512, B=16, E=768, H=32, d=24, BH=512, M=T*B=8192
#define LOG2E 1.4426950408889634f

// Scratch (device globals; no runtime allocation)
__device__ float g_q[512 * 512 * 24];     // [BH][T][24]
__device__ float g_k[512 * 512 * 24];
__device__ float g_v[512 * 512 * 24];
__device__ float g_attn[8192 * 768];      // [T*B][E]

// ---------------------------------------------------------------------------
// helpers
// ---------------------------------------------------------------------------
__device__ __forceinline__ void split_tf32(float x, uint32_t &h, uint32_t &l) {
    asm("cvt.rna.tf32.f32 %0, %1;" : "=r"(h) : "f"(x));
    float r = x - __uint_as_float(h);
    asm("cvt.rna.tf32.f32 %0, %1;" : "=r"(l) : "f"(r));
}

__device__ __forceinline__ void mma_tf32(float *c, const uint32_t *a, const uint32_t *b) {
    asm volatile(
        "mma.sync.aligned.m16n8k8.row.col.f32.tf32.tf32.f32 "
        "{%0,%1,%2,%3}, {%4,%5,%6,%7}, {%8,%9}, {%0,%1,%2,%3};"
        : "+f"(c[0]), "+f"(c[1]), "+f"(c[2]), "+f"(c[3])
        : "r"(a[0]), "r"(a[1]), "r"(a[2]), "r"(a[3]), "r"(b[0]), "r"(b[1]));
}

__device__ __forceinline__ void cpa16(float *s, const float *g) {
    uint32_t sa = (uint32_t)__cvta_generic_to_shared(s);
    asm volatile("cp.async.cg.shared.global [%0], [%1], 16;" :: "r"(sa), "l"(g));
}

// ---------------------------------------------------------------------------
// GEMM: C[M,N] = A[M,K] @ W[N,K]^T + bias, 3xTF32 split, BM=128 BN=64 BK=32
// MODE 0: QKV projection (blockIdx.z selects W/bias/dst; writes [BH][T][24])
// MODE 1: output projection (A = g_attn, writes row-major [M][N] to out)
// ---------------------------------------------------------------------------
template <int MODE>
__global__ __launch_bounds__(256, 2) void gemm3x(
    const float *__restrict__ X,
    const float *__restrict__ W0, const float *__restrict__ W1, const float *__restrict__ W2,
    const float *__restrict__ bb0, const float *__restrict__ bb1, const float *__restrict__ bb2,
    float *__restrict__ out)
{
    __shared__ float As[128][36];
    __shared__ float Bs[64][36];

    const int tid = threadIdx.x;
    const int lane = tid & 31, wid = tid >> 5;
    const int g = lane >> 2, t = lane & 3;
    const int wm = wid & 3, wn = wid >> 2;
    const int m0 = blockIdx.y * 128, n0 = blockIdx.x * 64;

    const float *Ap;
    const float *W;
    const float *bias;
    float *dst;
    float scale = 1.0f;
    if (MODE == 0) {
        int z = blockIdx.z;
        Ap = X;
        W = (z == 0) ? W0 : ((z == 1) ? W1 : W2);
        bias = (z == 0) ? bb0 : ((z == 1) ? bb1 : bb2);
        dst = (z == 0) ? g_q : ((z == 1) ? g_k : g_v);
        if (z == 0) scale = 0.2041241452319315f;  // 24^-0.5
    } else {
        Ap = g_attn;
        W = W0;
        bias = bb0;
        dst = out;
    }

    float c[2][4][4];
#pragma unroll
    for (int mt = 0; mt < 2; mt++)
#pragma unroll
        for (int nt = 0; nt < 4; nt++)
#pragma unroll
            for (int j = 0; j < 4; j++) c[mt][nt][j] = 0.f;

    for (int kk = 0; kk < 768; kk += 32) {
        __syncthreads();
#pragma unroll
        for (int i = 0; i < 4; i++) {
            int idx = tid + i * 256;
            int r = idx >> 3, c4 = (idx & 7) * 4;
            cpa16(&As[r][c4], Ap + (size_t)(m0 + r) * 768 + kk + c4);
        }
#pragma unroll
        for (int i = 0; i < 2; i++) {
            int idx = tid + i * 256;
            int r = idx >> 3, c4 = (idx & 7) * 4;
            cpa16(&Bs[r][c4], W + (size_t)(n0 + r) * 768 + kk + c4);
        }
        asm volatile("cp.async.commit_group;");
        asm volatile("cp.async.wait_group 0;");
        __syncthreads();

#pragma unroll
        for (int ks = 0; ks < 32; ks += 8) {
            uint32_t ah[2][4], al[2][4], bh[4][2], bl[4][2];
#pragma unroll
            for (int mt = 0; mt < 2; mt++) {
                int r = wm * 32 + mt * 16 + g;
                split_tf32(As[r][ks + t],         ah[mt][0], al[mt][0]);
                split_tf32(As[r + 8][ks + t],     ah[mt][1], al[mt][1]);
                split_tf32(As[r][ks + t + 4],     ah[mt][2], al[mt][2]);
                split_tf32(As[r + 8][ks + t + 4], ah[mt][3], al[mt][3]);
            }
#pragma unroll
            for (int nt = 0; nt < 4; nt++) {
                int n = wn * 32 + nt * 8 + g;
                split_tf32(Bs[n][ks + t],     bh[nt][0], bl[nt][0]);
                split_tf32(Bs[n][ks + t + 4], bh[nt][1], bl[nt][1]);
            }
#pragma unroll
            for (int mt = 0; mt < 2; mt++)
#pragma unroll
                for (int nt = 0; nt < 4; nt++) {
                    mma_tf32(c[mt][nt], ah[mt], bh[nt]);
                    mma_tf32(c[mt][nt], al[mt], bh[nt]);
                    mma_tf32(c[mt][nt], ah[mt], bl[nt]);
                }
        }
    }

#pragma unroll
    for (int mt = 0; mt < 2; mt++) {
#pragma unroll
        for (int nt = 0; nt < 4; nt++) {
#pragma unroll
            for (int j = 0; j < 4; j++) {
                int m = m0 + wm * 32 + mt * 16 + g + ((j >> 1) ? 8 : 0);
                int n = n0 + wn * 32 + nt * 8 + 2 * t + (j & 1);
                float v = (c[mt][nt][j] + bias[n]) * scale;
                if (MODE == 0) {
                    int tt = m >> 4, bb = m & 15;           // m = t*16 + b
                    int h = n / 24, dd = n - h * 24;        // n = h*24 + dd
                    dst[(((size_t)bb * 32 + h) * 512 + tt) * 24 + dd] = v;
                } else {
                    dst[(size_t)m * 768 + n] = v;
                }
            }
        }
    }
}

// ---------------------------------------------------------------------------
// Fused attention: per (bh, 64-row q tile). S = Q K^T + bias; online softmax;
// O += P V. All GEMMs via 3xTF32 mma. Bias streamed straight into fragments.
// ---------------------------------------------------------------------------
__global__ __launch_bounds__(128) void attn_kernel(const float *__restrict__ biasG)
{
    __shared__ float Qs[64][28];
    __shared__ float Ks[64][28];
    __shared__ float Vs[64][24];
    __shared__ float Ps[4][16][68];

    const int tid = threadIdx.x;
    const int lane = tid & 31, wid = tid >> 5;
    const int g = lane >> 2, t = lane & 3;
    const int bh = blockIdx.x;
    const int q0 = blockIdx.y * 64;

    const float *Qp = g_q + (size_t)bh * (512 * 24);
    const float *Kp = g_k + (size_t)bh * (512 * 24);
    const float *Vp = g_v + (size_t)bh * (512 * 24);
    const float *Bp = biasG + (size_t)bh * (512 * 512);

    for (int i = tid; i < 64 * 24; i += 128) {
        int r = i / 24, cc = i - r * 24;
        Qs[r][cc] = Qp[(q0 + r) * 24 + cc];
    }
    __syncthreads();

    // Q fragments are loop-invariant: precompute splits (3 k-steps cover d=24)
    uint32_t qh[3][4], ql[3][4];
    {
        int r = wid * 16 + g;
#pragma unroll
        for (int ks = 0; ks < 3; ks++) {
            int kc = ks * 8 + t;
            split_tf32(Qs[r][kc],         qh[ks][0], ql[ks][0]);
            split_tf32(Qs[r + 8][kc],     qh[ks][1], ql[ks][1]);
            split_tf32(Qs[r][kc + 4],     qh[ks][2], ql[ks][2]);
            split_tf32(Qs[r + 8][kc + 4], qh[ks][3], ql[ks][3]);
        }
    }

    float mrow0 = -1e30f, mrow1 = -1e30f;
    float lrow0 = 0.f, lrow1 = 0.f;
    float o[3][4];
#pragma unroll
    for (int vt = 0; vt < 3; vt++)
#pragma unroll
        for (int j = 0; j < 4; j++) o[vt][j] = 0.f;

    for (int s0 = 0; s0 < 512; s0 += 64) {
        __syncthreads();
        for (int i = tid; i < 64 * 24; i += 128) {
            int r = i / 24, cc = i - r * 24;
            Ks[r][cc] = Kp[(s0 + r) * 24 + cc];
            Vs[r][cc] = Vp[(s0 + r) * 24 + cc];
        }
        __syncthreads();

        float s[8][4];
#pragma unroll
        for (int nt = 0; nt < 8; nt++)
#pragma unroll
            for (int j = 0; j < 4; j++) s[nt][j] = 0.f;

#pragma unroll
        for (int ks = 0; ks < 3; ks++) {
#pragma unroll
            for (int nt = 0; nt < 8; nt++) {
                int n = nt * 8 + g;
                uint32_t kbh[2], kbl[2];
                split_tf32(Ks[n][ks * 8 + t],     kbh[0], kbl[0]);
                split_tf32(Ks[n][ks * 8 + t + 4], kbh[1], kbl[1]);
                mma_tf32(s[nt], qh[ks], kbh);
                mma_tf32(s[nt], ql[ks], kbh);
                mma_tf32(s[nt], qh[ks], kbl);
            }
        }

        // bias: fully coalesced float2 per fragment position (536MB stream)
        const int rg0 = q0 + wid * 16 + g;
#pragma unroll
        for (int nt = 0; nt < 8; nt++) {
            const float2 u0 = *(const float2 *)(Bp + (size_t)rg0 * 512 + s0 + nt * 8 + 2 * t);
            const float2 u1 = *(const float2 *)(Bp + (size_t)(rg0 + 8) * 512 + s0 + nt * 8 + 2 * t);
            s[nt][0] += u0.x; s[nt][1] += u0.y;
            s[nt][2] += u1.x; s[nt][3] += u1.y;
        }

        // online softmax (rows g and g+8 of this warp's 16-row slice)
        float tm0 = -1e30f, tm1 = -1e30f;
#pragma unroll
        for (int nt = 0; nt < 8; nt++) {
            tm0 = fmaxf(tm0, fmaxf(s[nt][0], s[nt][1]));
            tm1 = fmaxf(tm1, fmaxf(s[nt][2], s[nt][3]));
        }
        tm0 = fmaxf(tm0, __shfl_xor_sync(0xffffffffu, tm0, 1));
        tm0 = fmaxf(tm0, __shfl_xor_sync(0xffffffffu, tm0, 2));
        tm1 = fmaxf(tm1, __shfl_xor_sync(0xffffffffu, tm1, 1));
        tm1 = fmaxf(tm1, __shfl_xor_sync(0xffffffffu, tm1, 2));
        float mn0 = fmaxf(mrow0, tm0), mn1 = fmaxf(mrow1, tm1);
        float al0 = exp2f((mrow0 - mn0) * LOG2E);
        float al1 = exp2f((mrow1 - mn1) * LOG2E);
        float sum0 = 0.f, sum1 = 0.f;
#pragma unroll
        for (int nt = 0; nt < 8; nt++) {
            s[nt][0] = exp2f((s[nt][0] - mn0) * LOG2E);
            s[nt][1] = exp2f((s[nt][1] - mn0) * LOG2E);
            s[nt][2] = exp2f((s[nt][2] - mn1) * LOG2E);
            s[nt][3] = exp2f((s[nt][3] - mn1) * LOG2E);
            sum0 += s[nt][0] + s[nt][1];
            sum1 += s[nt][2] + s[nt][3];
        }
        sum0 += __shfl_xor_sync(0xffffffffu, sum0, 1);
        sum0 += __shfl_xor_sync(0xffffffffu, sum0, 2);
        sum1 += __shfl_xor_sync(0xffffffffu, sum1, 1);
        sum1 += __shfl_xor_sync(0xffffffffu, sum1, 2);
        lrow0 = lrow0 * al0 + sum0;
        lrow1 = lrow1 * al1 + sum1;
        mrow0 = mn0; mrow1 = mn1;
#pragma unroll
        for (int vt = 0; vt < 3; vt++) {
            o[vt][0] *= al0; o[vt][1] *= al0;
            o[vt][2] *= al1; o[vt][3] *= al1;
        }

        // P: C-fragment -> SMEM -> A-fragment (per-warp region; syncwarp only)
#pragma unroll
        for (int nt = 0; nt < 8; nt++) {
            *(float2 *)&Ps[wid][g][nt * 8 + 2 * t]     = make_float2(s[nt][0], s[nt][1]);
            *(float2 *)&Ps[wid][g + 8][nt * 8 + 2 * t] = make_float2(s[nt][2], s[nt][3]);
        }
        __syncwarp();

#pragma unroll
        for (int ks = 0; ks < 8; ks++) {
            int kc = ks * 8 + t;
            uint32_t ah2[4], al2[4];
            split_tf32(Ps[wid][g][kc],         ah2[0], al2[0]);
            split_tf32(Ps[wid][g + 8][kc],     ah2[1], al2[1]);
            split_tf32(Ps[wid][g][kc + 4],     ah2[2], al2[2]);
            split_tf32(Ps[wid][g + 8][kc + 4], ah2[3], al2[3]);
#pragma unroll
            for (int vt = 0; vt < 3; vt++) {
                uint32_t vbh[2], vbl[2];
                split_tf32(Vs[kc][vt * 8 + g],     vbh[0], vbl[0]);
                split_tf32(Vs[kc + 4][vt * 8 + g], vbh[1], vbl[1]);
                mma_tf32(o[vt], ah2, vbh);
                mma_tf32(o[vt], al2, vbh);
                mma_tf32(o[vt], ah2, vbl);
            }
        }
    }

    float inv0 = 1.f / lrow0;
    float inv1 = 1.f / lrow1;
    int tq = q0 + wid * 16 + g;
    int b_ = bh >> 5, hh = bh & 31;
#pragma unroll
    for (int vt = 0; vt < 3; vt++) {
        int col = hh * 24 + vt * 8 + 2 * t;
        float *d0 = &g_attn[((size_t)tq * 16 + b_) * 768 + col];
        d0[0] = o[vt][0] * inv0;
        d0[1] = o[vt][1] * inv0;
        float *d1 = &g_attn[((size_t)(tq + 8) * 16 + b_) * 768 + col];
        d1[0] = o[vt][2] * inv1;
        d1[1] = o[vt][3] * inv1;
    }
}

// ---------------------------------------------------------------------------
extern "C" void kernel_launch(void *const *d_in, const int *in_sizes, int n_in,
                              void *d_out, int out_size)
{
    const float *query = (const float *)d_in[0];
    const float *attn_bias = (const float *)d_in[1];
    const float *Wq = (const float *)d_in[2];
    const float *bq = (const float *)d_in[3];
    const float *Wk = (const float *)d_in[4];
    const float *bk = (const float *)d_in[5];
    const float *Wv = (const float *)d_in[6];
    const float *bv = (const float *)d_in[7];
    const float *Wo = (const float *)d_in[8];
    const float *bo = (const float *)d_in[9];
    float *out = (float *)d_out;

    dim3 gqkv(12, 64, 3);   // N-tiles, M-tiles, {Q,K,V}
    gemm3x<0><<<gqkv, 256>>>(query, Wq, Wk, Wv, bq, bk, bv, nullptr);

    dim3 gattn(512, 8);     // BH, q-tiles
    attn_kernel<<<gattn, 128>>>(attn_bias);

    dim3 gout(12, 64);
    gemm3x<1><<<gout, 256>>>(nullptr, Wo, nullptr, nullptr, bo, nullptr, nullptr, out);
}